// round 5
// baseline (speedup 1.0000x reference)
#include <cuda_runtime.h>
#include <math.h>

#define NB 16
#define NT 128
#define NC 64
#define NU 128
#define UNF 6
#define EPSV 1e-8f
#define TCHUNK 16

#define RANKS 4               // CTAs per cluster (per batch element)
#define JPC (NU / RANKS)      // 32 post-units per CTA
#define TPJ (128 / JPC)       // 4 threads per post-unit
#define PRE (NU / TPJ)        // 32 pre-units per thread

// Scratch (allocation-free rule: __device__ globals)
__device__ float g_sensN[NB * NT * NU];
__device__ float g_sensD[NB * NT * NU];
__device__ float g_SA[NC * NU];
__device__ float g_SB[NC * NU];
__device__ float g_SW[NC * NU];

__device__ __forceinline__ float tanha(float x) {
    float r;
    asm("tanh.approx.f32 %0, %1;" : "=f"(r) : "f"(x));
    return r;
}

__device__ __forceinline__ float softplusf(float x) {
    return log1pf(__expf(x));
}

__device__ __forceinline__ unsigned smem_u32(const void* p) {
    unsigned a;
    asm("{ .reg .u64 t; cvta.to.shared.u64 t, %1; cvt.u32.u64 %0, t; }"
        : "=r"(a) : "l"(p));
    return a;
}

// ---------------------------------------------------------------------------
// Kernel 0: transform sensory params once (fp32)
// ---------------------------------------------------------------------------
__global__ void k_sens_prep(const float* __restrict__ ss,
                            const float* __restrict__ smu,
                            const float* __restrict__ sw,
                            const float* __restrict__ serev) {
    int idx = blockIdx.x * blockDim.x + threadIdx.x;
    if (idx < NC * NU) {
        float a = 0.5f * ss[idx];
        g_SA[idx] = a;
        g_SB[idx] = -a * smu[idx];
        g_SW[idx] = softplusf(sw[idx]) * serev[idx];
    }
}

// ---------------------------------------------------------------------------
// Kernel 1: sensory pre-pass (fp32, fully parallel over b,t)
// ---------------------------------------------------------------------------
__global__ void __launch_bounds__(128) k_sensory(const float* __restrict__ x,
                                                 const float* __restrict__ iw,
                                                 const float* __restrict__ ib) {
    extern __shared__ float sm[];
    float* sSA = sm;
    float* sSB = sm + NC * NU;
    float* sSW = sm + 2 * NC * NU;
    float* xb  = sm + 3 * NC * NU;  // TCHUNK*NC

    int b  = blockIdx.x / (NT / TCHUNK);
    int t0 = (blockIdx.x % (NT / TCHUNK)) * TCHUNK;
    int tid = threadIdx.x;

    for (int idx = tid; idx < NC * NU; idx += 128) {
        sSA[idx] = g_SA[idx];
        sSB[idx] = g_SB[idx];
        sSW[idx] = g_SW[idx];
    }
    for (int idx = tid; idx < TCHUNK * NC; idx += 128) {
        int tt = idx / NC, i = idx % NC;
        xb[idx] = fmaf(x[(b * NT + t0 + tt) * NC + i], iw[i], ib[i]);
    }
    __syncthreads();

    int j = tid;
    for (int tt = 0; tt < TCHUNK; tt++) {
        float wn = 0.f, wd = 0.f;
#pragma unroll 8
        for (int i = 0; i < NC; i++) {
            float xv = xb[tt * NC + i];
            float y  = fmaf(sSA[i * NU + j], xv, sSB[i * NU + j]);
            float s  = fmaf(0.5f, tanha(y), 0.5f);
            float we = sSW[i * NU + j];
            wn = fmaf(we, s, wn);
            wd = fmaf(fabsf(we), s, wd);
        }
        int o = (b * NT + t0 + tt) * NU + j;
        g_sensN[o] = wn;
        g_sensD[o] = wd;
    }
}

// ---------------------------------------------------------------------------
// Kernel 2: main recurrence, cluster-parallel with mbarrier handshake.
// 4 CTAs per batch element; CTA `rank` owns post-units [rank*32, rank*32+32).
// Thread t: jloc=t/4, qtr=t%4; post-unit j over pre-units [qtr*32, qtr*32+32).
// Per unfold: writers (qtr==0) push 32 new v's to all 4 ranks' v-buffers,
// arrive release on the local mbarrier and on the 3 peers' mbarriers
// (count = 32*4 = 128 arrivals per barrier per unfold). All threads
// acquire-wait on the LOCAL mbarrier with per-unfold parity (try_wait with
// suspend-time hint, exactly the ptx_helpers loop shape). Writer arrival
// implies its warp finished reading the old buffer (shfl_xor full-mask sync),
// so the double-buffer swap is race-free. cluster.sync only at init and exit.
// ---------------------------------------------------------------------------
__global__ void __launch_bounds__(128, 1) __cluster_dims__(RANKS, 1, 1)
k_main(const float* __restrict__ h0,
       const float* __restrict__ gleak,
       const float* __restrict__ vleak,
       const float* __restrict__ cm,
       const float* __restrict__ sigma,
       const float* __restrict__ mu,
       const float* __restrict__ w,
       const float* __restrict__ erev,
       const float* __restrict__ ow,
       const float* __restrict__ ob,
       float* __restrict__ out,
       int write_hfinal) {
    __shared__ float vsm[2 * NU];
    __shared__ unsigned long long mbar;

    int rank = blockIdx.x;
    int b    = blockIdx.y;
    int t    = threadIdx.x;
    int jloc = t / TPJ;
    int qtr  = t % TPJ;
    int j    = rank * JPC + jloc;

    // ---- Prologue: this thread's 32 pre-unit params into registers ----
    float pa[PRE], pb[PRE], pw[PRE], pq[PRE];
    float swe = 0.f, swa = 0.f;
#pragma unroll
    for (int k = 0; k < PRE; k++) {
        int i   = qtr * PRE + k;
        int idx = i * NU + j;
        float sg = sigma[idx];
        pa[k] = 0.5f * sg;
        pb[k] = -pa[k] * mu[idx];
        float ww = softplusf(w[idx]) * erev[idx];
        pw[k] = ww;
        pq[k] = fabsf(ww);
        swe += ww;
        swa += pq[k];
    }
    swe += __shfl_xor_sync(0xFFFFFFFFu, swe, 1);
    swe += __shfl_xor_sync(0xFFFFFFFFu, swe, 2);
    swa += __shfl_xor_sync(0xFFFFFFFFu, swa, 1);
    swa += __shfl_xor_sync(0xFFFFFFFFu, swa, 2);

    float gl  = softplusf(gleak[j]);
    float cmt = softplusf(cm[j]) * (float)UNF;
    float K1  = fmaf(gl, vleak[j], 0.5f * swe);
    float K2  = cmt + gl + 0.5f * swa + EPSV;
    float owj = ow[j], obj = ob[j];

    // init v buffer 0 with h0 (local copy per CTA); init local mbarrier
    vsm[t] = h0[b * NU + t];
    if (t == 0) {
        unsigned mb = smem_u32(&mbar);
        asm volatile("mbarrier.init.shared.b64 [%0], %1;"
                     :: "r"(mb), "r"(128) : "memory");
    }
    __syncthreads();
    float vloc = vsm[j];

    // peer addresses (v-buffer all ranks; mbarrier peers only)
    unsigned vbase = smem_u32(vsm);
    unsigned bbase = smem_u32(&mbar);
    unsigned peerV[RANKS], peerB[RANKS];
#pragma unroll
    for (int r = 0; r < RANKS; r++) {
        asm("mapa.shared::cluster.u32 %0, %1, %2;"
            : "=r"(peerV[r]) : "r"(vbase), "r"(r));
        asm("mapa.shared::cluster.u32 %0, %1, %2;"
            : "=r"(peerB[r]) : "r"(bbase), "r"(r));
    }

    // all mbarriers initialized before any remote arrive
    asm volatile("barrier.cluster.arrive.aligned;" ::: "memory");
    asm volatile("barrier.cluster.wait.aligned;" ::: "memory");

    unsigned mbloc = bbase;
    unsigned phase = 0;
    int p = 0;

    // prefetch sensory terms for t=0
    int so = (b * NT) * NU + j;
    float curN = g_sensN[so];
    float curD = g_sensD[so];

#pragma unroll 1
    for (int ts = 0; ts < NT; ts++) {
        float base_n = K1 + curN;
        float base_d = K2 + curD;
        // prefetch next timestep's sensory terms (hidden behind 6 unfolds)
        if (ts + 1 < NT) {
            curN = g_sensN[so + NU];
            curD = g_sensD[so + NU];
        }
#pragma unroll 1
        for (int u = 0; u < UNF; u++) {
            const float4* v4 = (const float4*)(vsm + p * NU + qtr * PRE);
            float q = 0.f, r = 0.f;
#pragma unroll
            for (int c = 0; c < PRE / 4; c++) {
                float4 vv = v4[c];
                float t0 = tanha(fmaf(pa[4 * c + 0], vv.x, pb[4 * c + 0]));
                float t1 = tanha(fmaf(pa[4 * c + 1], vv.y, pb[4 * c + 1]));
                float t2 = tanha(fmaf(pa[4 * c + 2], vv.z, pb[4 * c + 2]));
                float t3 = tanha(fmaf(pa[4 * c + 3], vv.w, pb[4 * c + 3]));
                q = fmaf(pw[4 * c + 0], t0, q);
                r = fmaf(pq[4 * c + 0], t0, r);
                q = fmaf(pw[4 * c + 1], t1, q);
                r = fmaf(pq[4 * c + 1], t1, r);
                q = fmaf(pw[4 * c + 2], t2, q);
                r = fmaf(pq[4 * c + 2], t2, r);
                q = fmaf(pw[4 * c + 3], t3, q);
                r = fmaf(pq[4 * c + 3], t3, r);
            }
            q += __shfl_xor_sync(0xFFFFFFFFu, q, 1);
            q += __shfl_xor_sync(0xFFFFFFFFu, q, 2);
            r += __shfl_xor_sync(0xFFFFFFFFu, r, 1);
            r += __shfl_xor_sync(0xFFFFFFFFu, r, 2);

            float num = fmaf(cmt, vloc, base_n) + 0.5f * q;
            float den = base_d + 0.5f * r;
            vloc = __fdividef(num, den);

            // writers: push new v to every rank's buffer, then arrive on
            // local barrier (cta release) + 3 peers (cluster release)
            if (qtr == 0) {
                unsigned off = (unsigned)(((p ^ 1) * NU + j) * 4);
#pragma unroll
                for (int rr = 0; rr < RANKS; rr++) {
                    asm volatile("st.shared::cluster.f32 [%0], %1;"
                                 :: "r"(peerV[rr] + off), "f"(vloc) : "memory");
                }
                asm volatile(
                    "mbarrier.arrive.release.cta.shared::cta.b64 _, [%0];"
                    :: "r"(mbloc) : "memory");
#pragma unroll
                for (int rr = 0; rr < RANKS; rr++) {
                    if (rr != rank) {
                        asm volatile(
                            "mbarrier.arrive.release.cluster.shared::cluster.b64 _, [%0];"
                            :: "r"(peerB[rr]) : "memory");
                    }
                }
            }
            // all threads: acquire-wait on local mbarrier (parity per unfold)
            {
                unsigned done;
                asm volatile(
                    "{\n\t"
                    ".reg .pred p;\n\t"
                    "mbarrier.try_wait.parity.acquire.cluster.shared::cta.b64 p, [%1], %2, 0x989680;\n\t"
                    "selp.b32 %0, 1, 0, p;\n\t"
                    "}"
                    : "=r"(done) : "r"(mbloc), "r"(phase) : "memory");
                if (!done) {
                    asm volatile(
                        "{\n\t"
                        ".reg .pred P1;\n\t"
                        "WLT_%=:\n\t"
                        "mbarrier.try_wait.parity.acquire.cluster.shared::cta.b64 P1, [%0], %1, 0x989680;\n\t"
                        "@P1 bra.uni WDN_%=;\n\t"
                        "bra.uni WLT_%=;\n\t"
                        "WDN_%=:\n\t"
                        "}"
                        :: "r"(mbloc), "r"(phase) : "memory");
                }
            }
            phase ^= 1;
            p ^= 1;
        }
        if (qtr == 0) {
            out[so] = fmaf(vloc, owj, obj);
        }
        so += NU;
    }
    if (write_hfinal && qtr == 0) {
        out[NB * NT * NU + b * NU + j] = vloc;
    }

    // no CTA may exit while peers' remote ops could still target its smem
    asm volatile("barrier.cluster.arrive.aligned;" ::: "memory");
    asm volatile("barrier.cluster.wait.aligned;" ::: "memory");
}

// ---------------------------------------------------------------------------
extern "C" void kernel_launch(void* const* d_in, const int* in_sizes, int n_in,
                              void* d_out, int out_size) {
    const float* x      = (const float*)d_in[0];
    const float* h0     = (const float*)d_in[1];
    const float* gleak  = (const float*)d_in[2];
    const float* vleak  = (const float*)d_in[3];
    const float* cm     = (const float*)d_in[4];
    const float* sigma  = (const float*)d_in[5];
    const float* mu     = (const float*)d_in[6];
    const float* w      = (const float*)d_in[7];
    const float* erev   = (const float*)d_in[8];
    const float* ss     = (const float*)d_in[9];
    const float* smu    = (const float*)d_in[10];
    const float* sw     = (const float*)d_in[11];
    const float* serev  = (const float*)d_in[12];
    const float* iw     = (const float*)d_in[13];
    const float* ibias  = (const float*)d_in[14];
    const float* outw   = (const float*)d_in[15];
    const float* outb   = (const float*)d_in[16];

    const int SENS_SMEM = (3 * NC * NU + TCHUNK * NC) * (int)sizeof(float);  // 100 KB
    cudaFuncSetAttribute(k_sensory, cudaFuncAttributeMaxDynamicSharedMemorySize, SENS_SMEM);

    int write_hfinal = (out_size >= NB * NT * NU + NB * NU) ? 1 : 0;

    k_sens_prep<<<(NC * NU + 255) / 256, 256>>>(ss, smu, sw, serev);
    k_sensory<<<NB * (NT / TCHUNK), 128, SENS_SMEM>>>(x, iw, ibias);

    dim3 grid(RANKS, NB);
    k_main<<<grid, 128>>>(h0, gleak, vleak, cm, sigma, mu, w, erev,
                          outw, outb, (float*)d_out, write_hfinal);
}

// round 6
// speedup vs baseline: 1.1449x; 1.1449x over previous
#include <cuda_runtime.h>
#include <math.h>

#define NB 16
#define NT 128
#define NC 64
#define NU 128
#define UNF 6
#define EPSV 1e-8f
#define TCHUNK 16

#define RANKS 4               // CTAs per cluster (per batch element)
#define JPC (NU / RANKS)      // 32 post-units per CTA
#define TPJ (128 / JPC)       // 4 threads per post-unit
#define PRE (NU / TPJ)        // 32 pre-units per thread

// Scratch (allocation-free rule: __device__ globals)
__device__ float g_sensN[NB * NT * NU];
__device__ float g_sensD[NB * NT * NU];
__device__ float g_SA[NC * NU];
__device__ float g_SB[NC * NU];
__device__ float g_SW[NC * NU];

__device__ __forceinline__ float tanha(float x) {
    float r;
    asm("tanh.approx.f32 %0, %1;" : "=f"(r) : "f"(x));
    return r;
}

__device__ __forceinline__ float softplusf(float x) {
    return log1pf(__expf(x));
}

__device__ __forceinline__ unsigned smem_u32(const void* p) {
    unsigned a;
    asm("{ .reg .u64 t; cvta.to.shared.u64 t, %1; cvt.u32.u64 %0, t; }"
        : "=r"(a) : "l"(p));
    return a;
}

__device__ __forceinline__ void mbar_wait(unsigned addr, unsigned phase) {
    unsigned done;
    asm volatile(
        "{\n\t"
        ".reg .pred p;\n\t"
        "mbarrier.try_wait.parity.acquire.cluster.shared::cta.b64 p, [%1], %2, 0x989680;\n\t"
        "selp.b32 %0, 1, 0, p;\n\t"
        "}"
        : "=r"(done) : "r"(addr), "r"(phase) : "memory");
    if (!done) {
        asm volatile(
            "{\n\t"
            ".reg .pred P1;\n\t"
            "WLT_%=:\n\t"
            "mbarrier.try_wait.parity.acquire.cluster.shared::cta.b64 P1, [%0], %1, 0x989680;\n\t"
            "@P1 bra.uni WDN_%=;\n\t"
            "bra.uni WLT_%=;\n\t"
            "WDN_%=:\n\t"
            "}"
            :: "r"(addr), "r"(phase) : "memory");
    }
}

// ---------------------------------------------------------------------------
// Kernel 0: transform sensory params once (fp32)
// ---------------------------------------------------------------------------
__global__ void k_sens_prep(const float* __restrict__ ss,
                            const float* __restrict__ smu,
                            const float* __restrict__ sw,
                            const float* __restrict__ serev) {
    int idx = blockIdx.x * blockDim.x + threadIdx.x;
    if (idx < NC * NU) {
        float a = 0.5f * ss[idx];
        g_SA[idx] = a;
        g_SB[idx] = -a * smu[idx];
        g_SW[idx] = softplusf(sw[idx]) * serev[idx];
    }
}

// ---------------------------------------------------------------------------
// Kernel 1: sensory pre-pass (fp32, fully parallel over b,t)
// ---------------------------------------------------------------------------
__global__ void __launch_bounds__(128) k_sensory(const float* __restrict__ x,
                                                 const float* __restrict__ iw,
                                                 const float* __restrict__ ib) {
    extern __shared__ float sm[];
    float* sSA = sm;
    float* sSB = sm + NC * NU;
    float* sSW = sm + 2 * NC * NU;
    float* xb  = sm + 3 * NC * NU;  // TCHUNK*NC

    int b  = blockIdx.x / (NT / TCHUNK);
    int t0 = (blockIdx.x % (NT / TCHUNK)) * TCHUNK;
    int tid = threadIdx.x;

    for (int idx = tid; idx < NC * NU; idx += 128) {
        sSA[idx] = g_SA[idx];
        sSB[idx] = g_SB[idx];
        sSW[idx] = g_SW[idx];
    }
    for (int idx = tid; idx < TCHUNK * NC; idx += 128) {
        int tt = idx / NC, i = idx % NC;
        xb[idx] = fmaf(x[(b * NT + t0 + tt) * NC + i], iw[i], ib[i]);
    }
    __syncthreads();

    int j = tid;
    for (int tt = 0; tt < TCHUNK; tt++) {
        float wn = 0.f, wd = 0.f;
#pragma unroll 8
        for (int i = 0; i < NC; i++) {
            float xv = xb[tt * NC + i];
            float y  = fmaf(sSA[i * NU + j], xv, sSB[i * NU + j]);
            float s  = fmaf(0.5f, tanha(y), 0.5f);
            float we = sSW[i * NU + j];
            wn = fmaf(we, s, wn);
            wd = fmaf(fabsf(we), s, wd);
        }
        int o = (b * NT + t0 + tt) * NU + j;
        g_sensN[o] = wn;
        g_sensD[o] = wd;
    }
}

// ---------------------------------------------------------------------------
// Kernel 2: main recurrence, cluster-parallel, AGGREGATED mbarrier handshake.
// 4 CTAs per batch element; CTA `rank` owns post-units [rank*32, rank*32+32).
// Thread t: jloc=t/4, qtr=t%4; post-unit j over pre-units [qtr*32, qtr*32+32).
// Per unfold:
//   1. all threads compute; writers (qtr==0) push their new v to all 4 ranks'
//      v-buffers (st.shared::cluster)
//   2. __syncthreads()  -- orders all CTA stores before the signal
//   3. thread 0 ONLY: 1 local mbarrier.arrive + 3 remote
//      mbarrier.arrive.release.cluster (release cumulativity over the bar
//      covers the whole CTA's remote stores). 4 arrivals/barrier/unfold
//      (count=4) instead of 128 -- kills the atomic-serialization flood.
//   4. all threads acquire-try_wait on the LOCAL barrier.
// Two ping-pong barriers (unfold u uses barrier u&1) give ~2 unfolds of skew
// margin against premature next-phase arrivals. cluster.sync at init/exit only.
// ---------------------------------------------------------------------------
__global__ void __launch_bounds__(128, 1) __cluster_dims__(RANKS, 1, 1)
k_main(const float* __restrict__ h0,
       const float* __restrict__ gleak,
       const float* __restrict__ vleak,
       const float* __restrict__ cm,
       const float* __restrict__ sigma,
       const float* __restrict__ mu,
       const float* __restrict__ w,
       const float* __restrict__ erev,
       const float* __restrict__ ow,
       const float* __restrict__ ob,
       float* __restrict__ out,
       int write_hfinal) {
    __shared__ float vsm[2 * NU];
    __shared__ alignas(16) unsigned long long mbar[2];

    int rank = blockIdx.x;
    int b    = blockIdx.y;
    int t    = threadIdx.x;
    int jloc = t / TPJ;
    int qtr  = t % TPJ;
    int j    = rank * JPC + jloc;

    // ---- Prologue: this thread's 32 pre-unit params into registers ----
    // 0.5 factor folded into the weights.
    float pa[PRE], pb[PRE], pw[PRE], pq[PRE];
    float swe = 0.f, swa = 0.f;
#pragma unroll
    for (int k = 0; k < PRE; k++) {
        int i   = qtr * PRE + k;
        int idx = i * NU + j;
        float sg = sigma[idx];
        pa[k] = 0.5f * sg;
        pb[k] = -pa[k] * mu[idx];
        float ww = 0.5f * softplusf(w[idx]) * erev[idx];
        pw[k] = ww;
        pq[k] = fabsf(ww);
        swe += ww;
        swa += pq[k];
    }
    swe += __shfl_xor_sync(0xFFFFFFFFu, swe, 1);
    swe += __shfl_xor_sync(0xFFFFFFFFu, swe, 2);
    swa += __shfl_xor_sync(0xFFFFFFFFu, swa, 1);
    swa += __shfl_xor_sync(0xFFFFFFFFu, swa, 2);

    float gl  = softplusf(gleak[j]);
    float cmt = softplusf(cm[j]) * (float)UNF;
    float K1  = fmaf(gl, vleak[j], swe);           // swe already carries 0.5
    float K2  = cmt + gl + swa + EPSV;
    float owj = ow[j], obj = ob[j];

    // init v buffer 0 with h0 (local copy per CTA); init both mbarriers
    vsm[t] = h0[b * NU + t];
    if (t == 0) {
        asm volatile("mbarrier.init.shared.b64 [%0], %1;"
                     :: "r"(smem_u32(&mbar[0])), "r"(RANKS) : "memory");
        asm volatile("mbarrier.init.shared.b64 [%0], %1;"
                     :: "r"(smem_u32(&mbar[1])), "r"(RANKS) : "memory");
    }
    __syncthreads();
    float vloc = vsm[j];

    // peer addresses for all 4 ranks
    unsigned vbase = smem_u32(vsm);
    unsigned b0 = smem_u32(&mbar[0]);
    unsigned b1 = smem_u32(&mbar[1]);
    unsigned peerV[RANKS], peerB0[RANKS], peerB1[RANKS];
#pragma unroll
    for (int r = 0; r < RANKS; r++) {
        asm("mapa.shared::cluster.u32 %0, %1, %2;"
            : "=r"(peerV[r]) : "r"(vbase), "r"(r));
        asm("mapa.shared::cluster.u32 %0, %1, %2;"
            : "=r"(peerB0[r]) : "r"(b0), "r"(r));
        asm("mapa.shared::cluster.u32 %0, %1, %2;"
            : "=r"(peerB1[r]) : "r"(b1), "r"(r));
    }

    // all mbarriers initialized before any remote arrive
    asm volatile("barrier.cluster.arrive.aligned;" ::: "memory");
    asm volatile("barrier.cluster.wait.aligned;" ::: "memory");

    unsigned ph0 = 0, ph1 = 0;
    int bsel = 0;
    int p = 0;

    // prefetch sensory terms for t=0
    int so = (b * NT) * NU + j;
    float curN = g_sensN[so];
    float curD = g_sensD[so];

#pragma unroll 1
    for (int ts = 0; ts < NT; ts++) {
        float base_n = K1 + curN;
        float base_d = K2 + curD;
        if (ts + 1 < NT) {
            curN = g_sensN[so + NU];
            curD = g_sensD[so + NU];
        }
#pragma unroll 1
        for (int u = 0; u < UNF; u++) {
            const float4* v4 = (const float4*)(vsm + p * NU + qtr * PRE);
            float q = 0.f, r = 0.f;
#pragma unroll
            for (int c = 0; c < PRE / 4; c++) {
                float4 vv = v4[c];
                float t0 = tanha(fmaf(pa[4 * c + 0], vv.x, pb[4 * c + 0]));
                float t1 = tanha(fmaf(pa[4 * c + 1], vv.y, pb[4 * c + 1]));
                float t2 = tanha(fmaf(pa[4 * c + 2], vv.z, pb[4 * c + 2]));
                float t3 = tanha(fmaf(pa[4 * c + 3], vv.w, pb[4 * c + 3]));
                q = fmaf(pw[4 * c + 0], t0, q);
                r = fmaf(pq[4 * c + 0], t0, r);
                q = fmaf(pw[4 * c + 1], t1, q);
                r = fmaf(pq[4 * c + 1], t1, r);
                q = fmaf(pw[4 * c + 2], t2, q);
                r = fmaf(pq[4 * c + 2], t2, r);
                q = fmaf(pw[4 * c + 3], t3, q);
                r = fmaf(pq[4 * c + 3], t3, r);
            }
            q += __shfl_xor_sync(0xFFFFFFFFu, q, 1);
            q += __shfl_xor_sync(0xFFFFFFFFu, q, 2);
            r += __shfl_xor_sync(0xFFFFFFFFu, r, 1);
            r += __shfl_xor_sync(0xFFFFFFFFu, r, 2);

            float num = fmaf(cmt, vloc, base_n) + q;
            float den = base_d + r;
            vloc = __fdividef(num, den);

            // writers: push new v to every rank's buffer
            if (qtr == 0) {
                unsigned off = (unsigned)(((p ^ 1) * NU + j) * 4);
#pragma unroll
                for (int rr = 0; rr < RANKS; rr++) {
                    asm volatile("st.shared::cluster.f32 [%0], %1;"
                                 :: "r"(peerV[rr] + off), "f"(vloc) : "memory");
                }
            }
            // order the whole CTA's stores before the single signal
            __syncthreads();
            if (t == 0) {
                if (bsel == 0) {
                    asm volatile("mbarrier.arrive.shared.b64 _, [%0];"
                                 :: "r"(b0) : "memory");
#pragma unroll
                    for (int rr = 0; rr < RANKS; rr++) {
                        if (rr != rank)
                            asm volatile(
                                "mbarrier.arrive.release.cluster.shared::cluster.b64 _, [%0];"
                                :: "r"(peerB0[rr]) : "memory");
                    }
                } else {
                    asm volatile("mbarrier.arrive.shared.b64 _, [%0];"
                                 :: "r"(b1) : "memory");
#pragma unroll
                    for (int rr = 0; rr < RANKS; rr++) {
                        if (rr != rank)
                            asm volatile(
                                "mbarrier.arrive.release.cluster.shared::cluster.b64 _, [%0];"
                                :: "r"(peerB1[rr]) : "memory");
                    }
                }
            }
            // all threads: acquire-wait on local barrier (ping-pong + parity)
            if (bsel == 0) {
                mbar_wait(b0, ph0);
                ph0 ^= 1;
            } else {
                mbar_wait(b1, ph1);
                ph1 ^= 1;
            }
            bsel ^= 1;
            p ^= 1;
        }
        if (qtr == 0) {
            out[so] = fmaf(vloc, owj, obj);
        }
        so += NU;
    }
    if (write_hfinal && qtr == 0) {
        out[NB * NT * NU + b * NU + j] = vloc;
    }

    // no CTA may exit while peers' remote ops could still target its smem
    asm volatile("barrier.cluster.arrive.aligned;" ::: "memory");
    asm volatile("barrier.cluster.wait.aligned;" ::: "memory");
}

// ---------------------------------------------------------------------------
extern "C" void kernel_launch(void* const* d_in, const int* in_sizes, int n_in,
                              void* d_out, int out_size) {
    const float* x      = (const float*)d_in[0];
    const float* h0     = (const float*)d_in[1];
    const float* gleak  = (const float*)d_in[2];
    const float* vleak  = (const float*)d_in[3];
    const float* cm     = (const float*)d_in[4];
    const float* sigma  = (const float*)d_in[5];
    const float* mu     = (const float*)d_in[6];
    const float* w      = (const float*)d_in[7];
    const float* erev   = (const float*)d_in[8];
    const float* ss     = (const float*)d_in[9];
    const float* smu    = (const float*)d_in[10];
    const float* sw     = (const float*)d_in[11];
    const float* serev  = (const float*)d_in[12];
    const float* iw     = (const float*)d_in[13];
    const float* ibias  = (const float*)d_in[14];
    const float* outw   = (const float*)d_in[15];
    const float* outb   = (const float*)d_in[16];

    const int SENS_SMEM = (3 * NC * NU + TCHUNK * NC) * (int)sizeof(float);  // 100 KB
    cudaFuncSetAttribute(k_sensory, cudaFuncAttributeMaxDynamicSharedMemorySize, SENS_SMEM);

    int write_hfinal = (out_size >= NB * NT * NU + NB * NU) ? 1 : 0;

    k_sens_prep<<<(NC * NU + 255) / 256, 256>>>(ss, smu, sw, serev);
    k_sensory<<<NB * (NT / TCHUNK), 128, SENS_SMEM>>>(x, iw, ibias);

    dim3 grid(RANKS, NB);
    k_main<<<grid, 128>>>(h0, gleak, vleak, cm, sigma, mu, w, erev,
                          outw, outb, (float*)d_out, write_hfinal);
}

// round 7
// speedup vs baseline: 2.1322x; 1.8624x over previous
#include <cuda_runtime.h>
#include <math.h>

#define NB 16
#define NT 128
#define NC 64
#define NU 128
#define UNF 6
#define EPSV 1e-8f
#define TCHUNK 16

#define RANKS 4               // CTAs per cluster (per batch element)
#define JPC (NU / RANKS)      // 32 post-units per CTA
#define TPJ (128 / JPC)       // 4 threads per post-unit
#define PRE (NU / TPJ)        // 32 pre-units per thread
#define TXB (NU * 4)          // 512 bytes of v per unfold per rank

// Scratch (allocation-free rule: __device__ globals)
__device__ float g_sensN[NB * NT * NU];
__device__ float g_sensD[NB * NT * NU];
__device__ float g_SA[NC * NU];
__device__ float g_SB[NC * NU];
__device__ float g_SW[NC * NU];

__device__ __forceinline__ float tanha(float x) {
    float r;
    asm("tanh.approx.f32 %0, %1;" : "=f"(r) : "f"(x));
    return r;
}

__device__ __forceinline__ float softplusf(float x) {
    return log1pf(__expf(x));
}

__device__ __forceinline__ unsigned smem_u32(const void* p) {
    unsigned a;
    asm("{ .reg .u64 t; cvta.to.shared.u64 t, %1; cvt.u32.u64 %0, t; }"
        : "=r"(a) : "l"(p));
    return a;
}

__device__ __forceinline__ void mbar_wait(unsigned addr, unsigned phase) {
    unsigned done;
    asm volatile(
        "{\n\t"
        ".reg .pred p;\n\t"
        "mbarrier.try_wait.parity.acquire.cluster.shared::cta.b64 p, [%1], %2, 0x989680;\n\t"
        "selp.b32 %0, 1, 0, p;\n\t"
        "}"
        : "=r"(done) : "r"(addr), "r"(phase) : "memory");
    if (!done) {
        asm volatile(
            "{\n\t"
            ".reg .pred P1;\n\t"
            "WLT_%=:\n\t"
            "mbarrier.try_wait.parity.acquire.cluster.shared::cta.b64 P1, [%0], %1, 0x989680;\n\t"
            "@P1 bra.uni WDN_%=;\n\t"
            "bra.uni WLT_%=;\n\t"
            "WDN_%=:\n\t"
            "}"
            :: "r"(addr), "r"(phase) : "memory");
    }
}

// ---------------------------------------------------------------------------
// Kernel 0: transform sensory params once (fp32)
// ---------------------------------------------------------------------------
__global__ void k_sens_prep(const float* __restrict__ ss,
                            const float* __restrict__ smu,
                            const float* __restrict__ sw,
                            const float* __restrict__ serev) {
    int idx = blockIdx.x * blockDim.x + threadIdx.x;
    if (idx < NC * NU) {
        float a = 0.5f * ss[idx];
        g_SA[idx] = a;
        g_SB[idx] = -a * smu[idx];
        g_SW[idx] = softplusf(sw[idx]) * serev[idx];
    }
}

// ---------------------------------------------------------------------------
// Kernel 1: sensory pre-pass (fp32, fully parallel over b,t)
// ---------------------------------------------------------------------------
__global__ void __launch_bounds__(128) k_sensory(const float* __restrict__ x,
                                                 const float* __restrict__ iw,
                                                 const float* __restrict__ ib) {
    extern __shared__ float sm[];
    float* sSA = sm;
    float* sSB = sm + NC * NU;
    float* sSW = sm + 2 * NC * NU;
    float* xb  = sm + 3 * NC * NU;  // TCHUNK*NC

    int b  = blockIdx.x / (NT / TCHUNK);
    int t0 = (blockIdx.x % (NT / TCHUNK)) * TCHUNK;
    int tid = threadIdx.x;

    for (int idx = tid; idx < NC * NU; idx += 128) {
        sSA[idx] = g_SA[idx];
        sSB[idx] = g_SB[idx];
        sSW[idx] = g_SW[idx];
    }
    for (int idx = tid; idx < TCHUNK * NC; idx += 128) {
        int tt = idx / NC, i = idx % NC;
        xb[idx] = fmaf(x[(b * NT + t0 + tt) * NC + i], iw[i], ib[i]);
    }
    __syncthreads();

    int j = tid;
    for (int tt = 0; tt < TCHUNK; tt++) {
        float wn = 0.f, wd = 0.f;
#pragma unroll 8
        for (int i = 0; i < NC; i++) {
            float xv = xb[tt * NC + i];
            float y  = fmaf(sSA[i * NU + j], xv, sSB[i * NU + j]);
            float s  = fmaf(0.5f, tanha(y), 0.5f);
            float we = sSW[i * NU + j];
            wn = fmaf(we, s, wn);
            wd = fmaf(fabsf(we), s, wd);
        }
        int o = (b * NT + t0 + tt) * NU + j;
        g_sensN[o] = wn;
        g_sensD[o] = wd;
    }
}

// ---------------------------------------------------------------------------
// Kernel 2: main recurrence, cluster-parallel, st.async transaction barriers.
// 4 CTAs per batch element; CTA `rank` owns post-units [rank*32, rank*32+32).
// Thread t: jloc=t/4, qtr=t%4; post-unit j over pre-units [qtr*32, qtr*32+32).
// Per unfold:
//   - thread 0 arms the unfold's local mbarrier: arrive.expect_tx(512B)
//   - all threads compute; writers (qtr==0) push new v to all 4 ranks'
//     buffers via st.async.shared::cluster.mbarrier::complete_tx::bytes
//     (each 4B store counts down the destination's tx)
//   - all threads try_wait.parity.acquire on the LOCAL barrier; it flips
//     exactly when all 128 v's (512B) have physically landed.
// No __syncthreads in the loop. Race-freedom: a CTA passes barrier u only
// after every writer's store landed; each store is issued after its 4-lane
// group's shfl (reads of the old buffer complete), so unfold u+1's writes to
// that buffer cannot overtake unfold u's reads. Two ping-pong barriers bound
// the max 2-unfold lead; tx accounting is order-independent within a phase.
// cluster.sync only at init and exit.
// ---------------------------------------------------------------------------
__global__ void __launch_bounds__(128, 1) __cluster_dims__(RANKS, 1, 1)
k_main(const float* __restrict__ h0,
       const float* __restrict__ gleak,
       const float* __restrict__ vleak,
       const float* __restrict__ cm,
       const float* __restrict__ sigma,
       const float* __restrict__ mu,
       const float* __restrict__ w,
       const float* __restrict__ erev,
       const float* __restrict__ ow,
       const float* __restrict__ ob,
       float* __restrict__ out,
       int write_hfinal) {
    __shared__ float vsm[2 * NU];
    __shared__ alignas(16) unsigned long long mbar[2];

    int rank = blockIdx.x;
    int b    = blockIdx.y;
    int t    = threadIdx.x;
    int jloc = t / TPJ;
    int qtr  = t % TPJ;
    int j    = rank * JPC + jloc;

    // ---- Prologue: this thread's 32 pre-unit params into registers ----
    // 0.5 factor folded into the weights.
    float pa[PRE], pb[PRE], pw[PRE], pq[PRE];
    float swe = 0.f, swa = 0.f;
#pragma unroll
    for (int k = 0; k < PRE; k++) {
        int i   = qtr * PRE + k;
        int idx = i * NU + j;
        float sg = sigma[idx];
        pa[k] = 0.5f * sg;
        pb[k] = -pa[k] * mu[idx];
        float ww = 0.5f * softplusf(w[idx]) * erev[idx];
        pw[k] = ww;
        pq[k] = fabsf(ww);
        swe += ww;
        swa += pq[k];
    }
    swe += __shfl_xor_sync(0xFFFFFFFFu, swe, 1);
    swe += __shfl_xor_sync(0xFFFFFFFFu, swe, 2);
    swa += __shfl_xor_sync(0xFFFFFFFFu, swa, 1);
    swa += __shfl_xor_sync(0xFFFFFFFFu, swa, 2);

    float gl  = softplusf(gleak[j]);
    float cmt = softplusf(cm[j]) * (float)UNF;
    float K1  = fmaf(gl, vleak[j], swe);           // swe already carries 0.5
    float K2  = cmt + gl + swa + EPSV;
    float owj = ow[j], obj = ob[j];

    // init v buffer 0 with h0 (local copy per CTA); init both mbarriers
    vsm[t] = h0[b * NU + t];
    if (t == 0) {
        asm volatile("mbarrier.init.shared.b64 [%0], %1;"
                     :: "r"(smem_u32(&mbar[0])), "r"(1) : "memory");
        asm volatile("mbarrier.init.shared.b64 [%0], %1;"
                     :: "r"(smem_u32(&mbar[1])), "r"(1) : "memory");
    }
    __syncthreads();
    float vloc = vsm[j];

    // peer addresses for all 4 ranks
    unsigned vbase = smem_u32(vsm);
    unsigned b0 = smem_u32(&mbar[0]);
    unsigned b1 = smem_u32(&mbar[1]);
    unsigned peerV[RANKS], peerB0[RANKS], peerB1[RANKS];
#pragma unroll
    for (int r = 0; r < RANKS; r++) {
        asm("mapa.shared::cluster.u32 %0, %1, %2;"
            : "=r"(peerV[r]) : "r"(vbase), "r"(r));
        asm("mapa.shared::cluster.u32 %0, %1, %2;"
            : "=r"(peerB0[r]) : "r"(b0), "r"(r));
        asm("mapa.shared::cluster.u32 %0, %1, %2;"
            : "=r"(peerB1[r]) : "r"(b1), "r"(r));
    }

    // all mbarriers initialized before any remote store/complete_tx
    asm volatile("barrier.cluster.arrive.aligned;" ::: "memory");
    asm volatile("barrier.cluster.wait.aligned;" ::: "memory");

    unsigned ph0 = 0, ph1 = 0;
    int bsel = 0;
    int p = 0;

    // prefetch sensory terms for t=0
    int so = (b * NT) * NU + j;
    float curN = g_sensN[so];
    float curD = g_sensD[so];

#pragma unroll 1
    for (int ts = 0; ts < NT; ts++) {
        float base_n = K1 + curN;
        float base_d = K2 + curD;
        if (ts + 1 < NT) {
            curN = g_sensN[so + NU];
            curD = g_sensD[so + NU];
        }
#pragma unroll 1
        for (int u = 0; u < UNF; u++) {
            // arm this unfold's barrier early (1 arrival + 512B expected)
            if (t == 0) {
                unsigned bb = bsel ? b1 : b0;
                asm volatile(
                    "mbarrier.arrive.expect_tx.shared.b64 _, [%0], %1;"
                    :: "r"(bb), "r"(TXB) : "memory");
            }

            const float4* v4 = (const float4*)(vsm + p * NU + qtr * PRE);
            float q = 0.f, r = 0.f;
#pragma unroll
            for (int c = 0; c < PRE / 4; c++) {
                float4 vv = v4[c];
                float t0 = tanha(fmaf(pa[4 * c + 0], vv.x, pb[4 * c + 0]));
                float t1 = tanha(fmaf(pa[4 * c + 1], vv.y, pb[4 * c + 1]));
                float t2 = tanha(fmaf(pa[4 * c + 2], vv.z, pb[4 * c + 2]));
                float t3 = tanha(fmaf(pa[4 * c + 3], vv.w, pb[4 * c + 3]));
                q = fmaf(pw[4 * c + 0], t0, q);
                r = fmaf(pq[4 * c + 0], t0, r);
                q = fmaf(pw[4 * c + 1], t1, q);
                r = fmaf(pq[4 * c + 1], t1, r);
                q = fmaf(pw[4 * c + 2], t2, q);
                r = fmaf(pq[4 * c + 2], t2, r);
                q = fmaf(pw[4 * c + 3], t3, q);
                r = fmaf(pq[4 * c + 3], t3, r);
            }
            q += __shfl_xor_sync(0xFFFFFFFFu, q, 1);
            q += __shfl_xor_sync(0xFFFFFFFFu, q, 2);
            r += __shfl_xor_sync(0xFFFFFFFFu, r, 1);
            r += __shfl_xor_sync(0xFFFFFFFFu, r, 2);

            float num = fmaf(cmt, vloc, base_n) + q;
            float den = base_d + r;
            vloc = __fdividef(num, den);

            // writers: st.async the new v into every rank's buffer; each
            // store carries a 4B complete_tx on the destination's barrier
            if (qtr == 0) {
                unsigned off = (unsigned)(((p ^ 1) * NU + j) * 4);
                if (bsel == 0) {
#pragma unroll
                    for (int rr = 0; rr < RANKS; rr++) {
                        asm volatile(
                            "st.async.shared::cluster.mbarrier::complete_tx::bytes.f32 "
                            "[%0], %1, [%2];"
                            :: "r"(peerV[rr] + off), "f"(vloc), "r"(peerB0[rr])
                            : "memory");
                    }
                } else {
#pragma unroll
                    for (int rr = 0; rr < RANKS; rr++) {
                        asm volatile(
                            "st.async.shared::cluster.mbarrier::complete_tx::bytes.f32 "
                            "[%0], %1, [%2];"
                            :: "r"(peerV[rr] + off), "f"(vloc), "r"(peerB1[rr])
                            : "memory");
                    }
                }
            }
            // wait for all 128 v's to land in the LOCAL buffer
            if (bsel == 0) {
                mbar_wait(b0, ph0);
                ph0 ^= 1;
            } else {
                mbar_wait(b1, ph1);
                ph1 ^= 1;
            }
            bsel ^= 1;
            p ^= 1;
        }
        if (qtr == 0) {
            out[so] = fmaf(vloc, owj, obj);
        }
        so += NU;
    }
    if (write_hfinal && qtr == 0) {
        out[NB * NT * NU + b * NU + j] = vloc;
    }

    // no CTA may exit while peers' remote ops could still target its smem
    asm volatile("barrier.cluster.arrive.aligned;" ::: "memory");
    asm volatile("barrier.cluster.wait.aligned;" ::: "memory");
}

// ---------------------------------------------------------------------------
extern "C" void kernel_launch(void* const* d_in, const int* in_sizes, int n_in,
                              void* d_out, int out_size) {
    const float* x      = (const float*)d_in[0];
    const float* h0     = (const float*)d_in[1];
    const float* gleak  = (const float*)d_in[2];
    const float* vleak  = (const float*)d_in[3];
    const float* cm     = (const float*)d_in[4];
    const float* sigma  = (const float*)d_in[5];
    const float* mu     = (const float*)d_in[6];
    const float* w      = (const float*)d_in[7];
    const float* erev   = (const float*)d_in[8];
    const float* ss     = (const float*)d_in[9];
    const float* smu    = (const float*)d_in[10];
    const float* sw     = (const float*)d_in[11];
    const float* serev  = (const float*)d_in[12];
    const float* iw     = (const float*)d_in[13];
    const float* ibias  = (const float*)d_in[14];
    const float* outw   = (const float*)d_in[15];
    const float* outb   = (const float*)d_in[16];

    const int SENS_SMEM = (3 * NC * NU + TCHUNK * NC) * (int)sizeof(float);  // 100 KB
    cudaFuncSetAttribute(k_sensory, cudaFuncAttributeMaxDynamicSharedMemorySize, SENS_SMEM);

    int write_hfinal = (out_size >= NB * NT * NU + NB * NU) ? 1 : 0;

    k_sens_prep<<<(NC * NU + 255) / 256, 256>>>(ss, smu, sw, serev);
    k_sensory<<<NB * (NT / TCHUNK), 128, SENS_SMEM>>>(x, iw, ibias);

    dim3 grid(RANKS, NB);
    k_main<<<grid, 128>>>(h0, gleak, vleak, cm, sigma, mu, w, erev,
                          outw, outb, (float*)d_out, write_hfinal);
}